// round 15
// baseline (speedup 1.0000x reference)
#include <cuda_runtime.h>
#include <math.h>
#include <float.h>

#define FI 256
#define FO 256
#define AA 16
#define RR 32
#define TK 16
#define MAXN 20000
#define NBBN 592
#define SDEPTH 12          // staged entries per merge list (overflow -> global fallback)
#define SSTR (SDEPTH + 1)  // smem stride (bank-safe)

// ---------------- static device scratch (no allocations allowed) ----------------
__device__ float g_key[MAXN * AA];
__device__ float g_query[MAXN * AA];
__device__ float g_newh[(size_t)MAXN * FO];
__device__ float g_finalpre[(size_t)MAXN * FO];
__device__ float g_las[MAXN];
__device__ unsigned long long g_adjsorted[(size_t)MAXN * RR];
__device__ double g_sum[FO], g_sumsq[FO];
__device__ unsigned g_cnt[(MAXN + 63) / 64];   // epoch counters ((old&3)==3 -> last of 4; no reset needed)

// monotone float <-> uint mapping (for descending-order max selection)
__device__ __forceinline__ unsigned ordu(float f) {
    unsigned u = __float_as_uint(f);
    return (u & 0x80000000u) ? ~u : (u | 0x80000000u);
}
__device__ __forceinline__ float unordu(unsigned u) {
    return (u & 0x80000000u) ? __uint_as_float(u ^ 0x80000000u) : __uint_as_float(~u);
}

__device__ __forceinline__ void cp16(unsigned dst, const void* src) {
    asm volatile("cp.async.cg.shared.global [%0], [%1], 16;" :: "r"(dst), "l"(src));
}
__device__ __forceinline__ void cp_commit() {
    asm volatile("cp.async.commit_group;");
}
__device__ __forceinline__ void cp_wait0() {
    asm volatile("cp.async.wait_group 0;" ::: "memory");
}

// descending warp bitonic sort of 64-bit keys (unique keys -> deterministic total order)
__device__ __forceinline__ unsigned long long warp_sort_desc(unsigned long long key, int lane) {
#pragma unroll
    for (int size = 2; size <= 32; size <<= 1) {
#pragma unroll
        for (int stride = size >> 1; stride; stride >>= 1) {
            unsigned long long other = __shfl_xor_sync(~0u, key, stride);
            bool down = ((lane & size) == 0);
            bool isUpper = ((lane & stride) != 0);
            bool keepMax = down ^ isUpper;
            unsigned long long mx = key > other ? key : other;
            unsigned long long mn = key > other ? other : key;
            key = keepMax ? mx : mn;
        }
    }
    return key;
}

// =====================================================================================
// fused GEMM + KQ (+ las tail) kernel:
//   blockIdx.y in [0,4): new_h 64x64 tile; last finisher of each row-group runs las
//   blockIdx.y == 4: K/Q 64x32 tile
// =====================================================================================

// ---- KQ part: 64x32 tile (cols = [Key(16) | Query(16)]); K/Q rounding is tolerance-safe ----
__device__ __forceinline__ void kq_body(char* smraw, int bx,
                                        const float* __restrict__ x,
                                        const float* __restrict__ Wk, const float* __restrict__ Bk,
                                        const float* __restrict__ Wq, const float* __restrict__ Bq,
                                        int N) {
    float (*As)[64][20] = reinterpret_cast<float (*)[64][20]>(smraw);
    float (*Bs)[16][32] = reinterpret_cast<float (*)[16][32]>(smraw + 2 * 64 * 20 * 4);
    int tid = threadIdx.x;
    int m0 = bx * 64;
    if (bx == 0) {            // fold former k_bnzero launch
        g_sum[tid] = 0.0; g_sum[tid + 128] = 0.0;
        g_sumsq[tid] = 0.0; g_sumsq[tid + 128] = 0.0;
    }
    int tx = tid & 7, ty = tid >> 3;

    int ca0 = tid * 2, ca1 = tid * 2 + 1;
    int arow0 = ca0 >> 2, ac40 = ca0 & 3;
    int arow1 = ca1 >> 2, ac41 = ca1 & 3;
    int ag0 = m0 + arow0; if (ag0 > N - 1) ag0 = N - 1;
    int ag1 = m0 + arow1; if (ag1 > N - 1) ag1 = N - 1;
    const float* asrc0 = x + (size_t)ag0 * FI + ac40 * 4;
    const float* asrc1 = x + (size_t)ag1 * FI + ac41 * 4;
    unsigned adst00 = (unsigned)__cvta_generic_to_shared(&As[0][arow0][ac40 * 4]);
    unsigned adst01 = (unsigned)__cvta_generic_to_shared(&As[0][arow1][ac41 * 4]);
    unsigned adst10 = (unsigned)__cvta_generic_to_shared(&As[1][arow0][ac40 * 4]);
    unsigned adst11 = (unsigned)__cvta_generic_to_shared(&As[1][arow1][ac41 * 4]);

    int brr = tid >> 3, bcc = tid & 7;  // row, chunk (0-3: Wk, 4-7: Wq)
    const float* bsrc = (bcc < 4) ? (Wk + (size_t)brr * AA + bcc * 4)
                                  : (Wq + (size_t)brr * AA + (bcc - 4) * 4);
    int bcol = (bcc < 4) ? bcc * 4 : 16 + (bcc - 4) * 4;
    unsigned bdst0 = (unsigned)__cvta_generic_to_shared(&Bs[0][brr][bcol]);
    unsigned bdst1 = (unsigned)__cvta_generic_to_shared(&Bs[1][brr][bcol]);

    float acc[4][4];
#pragma unroll
    for (int i = 0; i < 4; i++)
#pragma unroll
        for (int j = 0; j < 4; j++) acc[i][j] = 0.f;

    cp16(adst00, asrc0);
    cp16(adst01, asrc1);
    cp16(bdst0, bsrc);
    cp_commit();

    for (int s = 0; s < FI / 16; s++) {
        cp_wait0();
        __syncthreads();
        if (s + 1 < FI / 16) {
            int k0n = (s + 1) * 16;
            if (((s + 1) & 1) == 0) {
                cp16(adst00, asrc0 + k0n);
                cp16(adst01, asrc1 + k0n);
                cp16(bdst0, bsrc + (size_t)k0n * AA);
            } else {
                cp16(adst10, asrc0 + k0n);
                cp16(adst11, asrc1 + k0n);
                cp16(bdst1, bsrc + (size_t)k0n * AA);
            }
            cp_commit();
        }
        int bf = s & 1;
#pragma unroll
        for (int kk = 0; kk < 16; kk++) {
            float a0 = As[bf][ty * 4 + 0][kk];
            float a1 = As[bf][ty * 4 + 1][kk];
            float a2 = As[bf][ty * 4 + 2][kk];
            float a3 = As[bf][ty * 4 + 3][kk];
            float4 b = *(const float4*)&Bs[bf][kk][tx * 4];
            acc[0][0] = fmaf(a0, b.x, acc[0][0]); acc[0][1] = fmaf(a0, b.y, acc[0][1]);
            acc[0][2] = fmaf(a0, b.z, acc[0][2]); acc[0][3] = fmaf(a0, b.w, acc[0][3]);
            acc[1][0] = fmaf(a1, b.x, acc[1][0]); acc[1][1] = fmaf(a1, b.y, acc[1][1]);
            acc[1][2] = fmaf(a1, b.z, acc[1][2]); acc[1][3] = fmaf(a1, b.w, acc[1][3]);
            acc[2][0] = fmaf(a2, b.x, acc[2][0]); acc[2][1] = fmaf(a2, b.y, acc[2][1]);
            acc[2][2] = fmaf(a2, b.z, acc[2][2]); acc[2][3] = fmaf(a2, b.w, acc[2][3]);
            acc[3][0] = fmaf(a3, b.x, acc[3][0]); acc[3][1] = fmaf(a3, b.y, acc[3][1]);
            acc[3][2] = fmaf(a3, b.z, acc[3][2]); acc[3][3] = fmaf(a3, b.w, acc[3][3]);
        }
        __syncthreads();
    }
    int c0 = tx * 4;
#pragma unroll
    for (int i = 0; i < 4; i++) {
        int gr = m0 + ty * 4 + i;
        if (gr < N) {
            float4 v;
            if (tx < 4) {
                v.x = acc[i][0] + Bk[c0 + 0]; v.y = acc[i][1] + Bk[c0 + 1];
                v.z = acc[i][2] + Bk[c0 + 2]; v.w = acc[i][3] + Bk[c0 + 3];
                *(float4*)(g_key + (size_t)gr * AA + c0) = v;
            } else {
                int c = c0 - 16;
                v.x = acc[i][0] + Bq[c + 0]; v.y = acc[i][1] + Bq[c + 1];
                v.z = acc[i][2] + Bq[c + 2]; v.w = acc[i][3] + Bq[c + 3];
                *(float4*)(g_query + (size_t)gr * AA + c) = v;
            }
        }
    }
}

// ---- GEMM part: 64x64 tile, 4x8 micro. Ascending-k FMA chain per element + bias at end:
//      rounding structure MUST stay (la_s bit-match depends on newh bits). ----
__global__ __launch_bounds__(128, 8) void k_gemm_kq(const float* __restrict__ x,
                                                    const float* __restrict__ W,
                                                    const float* __restrict__ B,
                                                    const float* __restrict__ Wk, const float* __restrict__ Bk,
                                                    const float* __restrict__ Wq, const float* __restrict__ Bq,
                                                    const float* __restrict__ la, const float* __restrict__ Bla,
                                                    int N) {
    __shared__ __align__(16) char smraw[2 * 64 * 20 * 4 + 2 * 16 * 64 * 4];
    __shared__ unsigned s_oldc;
    if (blockIdx.y == 4) {
        kq_body(smraw, blockIdx.x, x, Wk, Bk, Wq, Bq, N);
        return;
    }
    float (*As)[64][20] = reinterpret_cast<float (*)[64][20]>(smraw);
    float (*Bs)[16][64] = reinterpret_cast<float (*)[16][64]>(smraw + 2 * 64 * 20 * 4);
    int tid = threadIdx.x;
    int m0 = blockIdx.x * 64;
    int n0 = blockIdx.y * 64;
    int tx = tid & 7, ty = tid >> 3;

    int ca0 = tid * 2, ca1 = tid * 2 + 1;
    int arow0 = ca0 >> 2, ac40 = ca0 & 3;
    int arow1 = ca1 >> 2, ac41 = ca1 & 3;
    int ag0 = m0 + arow0; if (ag0 > N - 1) ag0 = N - 1;
    int ag1 = m0 + arow1; if (ag1 > N - 1) ag1 = N - 1;
    const float* asrc0 = x + (size_t)ag0 * FI + ac40 * 4;
    const float* asrc1 = x + (size_t)ag1 * FI + ac41 * 4;
    unsigned adst00 = (unsigned)__cvta_generic_to_shared(&As[0][arow0][ac40 * 4]);
    unsigned adst01 = (unsigned)__cvta_generic_to_shared(&As[0][arow1][ac41 * 4]);
    unsigned adst10 = (unsigned)__cvta_generic_to_shared(&As[1][arow0][ac40 * 4]);
    unsigned adst11 = (unsigned)__cvta_generic_to_shared(&As[1][arow1][ac41 * 4]);

    int f0 = tid * 2, f1 = tid * 2 + 1;
    int br0 = f0 >> 4, bc0 = (f0 & 15) * 4;
    int br1 = f1 >> 4, bc1 = (f1 & 15) * 4;
    const float* bsrc0 = W + (size_t)br0 * FO + n0 + bc0;
    const float* bsrc1 = W + (size_t)br1 * FO + n0 + bc1;
    unsigned bdst00 = (unsigned)__cvta_generic_to_shared(&Bs[0][br0][bc0]);
    unsigned bdst01 = (unsigned)__cvta_generic_to_shared(&Bs[0][br1][bc1]);
    unsigned bdst10 = (unsigned)__cvta_generic_to_shared(&Bs[1][br0][bc0]);
    unsigned bdst11 = (unsigned)__cvta_generic_to_shared(&Bs[1][br1][bc1]);

    float acc[4][8];
#pragma unroll
    for (int i = 0; i < 4; i++)
#pragma unroll
        for (int j = 0; j < 8; j++) acc[i][j] = 0.f;

    cp16(adst00, asrc0);
    cp16(adst01, asrc1);
    cp16(bdst00, bsrc0);
    cp16(bdst01, bsrc1);
    cp_commit();

    for (int s = 0; s < FI / 16; s++) {
        cp_wait0();
        __syncthreads();
        if (s + 1 < FI / 16) {
            int k0n = (s + 1) * 16;
            if (((s + 1) & 1) == 0) {
                cp16(adst00, asrc0 + k0n);
                cp16(adst01, asrc1 + k0n);
                cp16(bdst00, bsrc0 + (size_t)k0n * FO);
                cp16(bdst01, bsrc1 + (size_t)k0n * FO);
            } else {
                cp16(adst10, asrc0 + k0n);
                cp16(adst11, asrc1 + k0n);
                cp16(bdst10, bsrc0 + (size_t)k0n * FO);
                cp16(bdst11, bsrc1 + (size_t)k0n * FO);
            }
            cp_commit();
        }
        int bf = s & 1;
#pragma unroll
        for (int kk = 0; kk < 16; kk++) {
            float a0 = As[bf][ty * 4 + 0][kk];
            float a1 = As[bf][ty * 4 + 1][kk];
            float a2 = As[bf][ty * 4 + 2][kk];
            float a3 = As[bf][ty * 4 + 3][kk];
            float4 blo = *(const float4*)&Bs[bf][kk][tx * 4];
            float4 bhi = *(const float4*)&Bs[bf][kk][32 + tx * 4];
            acc[0][0] = fmaf(a0, blo.x, acc[0][0]); acc[0][1] = fmaf(a0, blo.y, acc[0][1]);
            acc[0][2] = fmaf(a0, blo.z, acc[0][2]); acc[0][3] = fmaf(a0, blo.w, acc[0][3]);
            acc[0][4] = fmaf(a0, bhi.x, acc[0][4]); acc[0][5] = fmaf(a0, bhi.y, acc[0][5]);
            acc[0][6] = fmaf(a0, bhi.z, acc[0][6]); acc[0][7] = fmaf(a0, bhi.w, acc[0][7]);
            acc[1][0] = fmaf(a1, blo.x, acc[1][0]); acc[1][1] = fmaf(a1, blo.y, acc[1][1]);
            acc[1][2] = fmaf(a1, blo.z, acc[1][2]); acc[1][3] = fmaf(a1, blo.w, acc[1][3]);
            acc[1][4] = fmaf(a1, bhi.x, acc[1][4]); acc[1][5] = fmaf(a1, bhi.y, acc[1][5]);
            acc[1][6] = fmaf(a1, bhi.z, acc[1][6]); acc[1][7] = fmaf(a1, bhi.w, acc[1][7]);
            acc[2][0] = fmaf(a2, blo.x, acc[2][0]); acc[2][1] = fmaf(a2, blo.y, acc[2][1]);
            acc[2][2] = fmaf(a2, blo.z, acc[2][2]); acc[2][3] = fmaf(a2, blo.w, acc[2][3]);
            acc[2][4] = fmaf(a2, bhi.x, acc[2][4]); acc[2][5] = fmaf(a2, bhi.y, acc[2][5]);
            acc[2][6] = fmaf(a2, bhi.z, acc[2][6]); acc[2][7] = fmaf(a2, bhi.w, acc[2][7]);
            acc[3][0] = fmaf(a3, blo.x, acc[3][0]); acc[3][1] = fmaf(a3, blo.y, acc[3][1]);
            acc[3][2] = fmaf(a3, blo.z, acc[3][2]); acc[3][3] = fmaf(a3, blo.w, acc[3][3]);
            acc[3][4] = fmaf(a3, bhi.x, acc[3][4]); acc[3][5] = fmaf(a3, bhi.y, acc[3][5]);
            acc[3][6] = fmaf(a3, bhi.z, acc[3][6]); acc[3][7] = fmaf(a3, bhi.w, acc[3][7]);
        }
    }
#pragma unroll
    for (int i = 0; i < 4; i++) {
        int gr = m0 + ty * 4 + i;
        if (gr < N) {
            int gc = n0 + tx * 4;
            float4 v0;
            v0.x = acc[i][0] + B[gc + 0]; v0.y = acc[i][1] + B[gc + 1];
            v0.z = acc[i][2] + B[gc + 2]; v0.w = acc[i][3] + B[gc + 3];
            *(float4*)(g_newh + (size_t)gr * FO + gc) = v0;
            int gc2 = n0 + 32 + tx * 4;
            float4 v1;
            v1.x = acc[i][4] + B[gc2 + 0]; v1.y = acc[i][5] + B[gc2 + 1];
            v1.z = acc[i][6] + B[gc2 + 2]; v1.w = acc[i][7] + B[gc2 + 3];
            *(float4*)(g_newh + (size_t)gr * FO + gc2) = v1;
        }
    }

    // ---- las tail: last of the 4 column-tile blocks computes la_s for this row-group ----
    // Release: make our newh stores visible, then count in.
    __threadfence();
    __syncthreads();
    if (tid == 0) s_oldc = atomicAdd(&g_cnt[blockIdx.x], 1u);
    __syncthreads();
    if ((s_oldc & 3u) == 3u) {
        __threadfence();                     // acquire: siblings' newh stores now visible
        float* sla = (float*)smraw;          // main-loop smem dead; reuse
        sla[tid] = la[tid];
        sla[tid + 128] = la[tid + 128];
        __syncthreads();
        float bla = Bla[0];
        int p = tid & 3;
#pragma unroll
        for (int pass = 0; pass < 2; pass++) {
            int rown = m0 + pass * 32 + (tid >> 2);
            int row = rown < N ? rown : N - 1;   // clamp: keep lanes active for shfl
            const float* h = g_newh + (size_t)row * FO + p;
            float a = 0.f;
            // NEON-gemv order: lane-p chain ascending, stride 4 (DO NOT TOUCH ORDER)
#pragma unroll 16
            for (int j = 0; j < 64; j++)
                a = fmaf(h[4 * j], sla[4 * j + p], a);
            float o1 = __shfl_down_sync(~0u, a, 1);
            float t01 = __fadd_rn(a, o1);        // p0: a0+a1 ; p2: a2+a3
            float t23 = __shfl_down_sync(~0u, t01, 2);
            if (rown < N && p == 0)
                g_las[row] = __fadd_rn(t01, t23) + bla;
        }
    }
}

// =====================================================================================
// fused ATT + SORTADJ kernel: blocks [0, nbSort) sort adj rows; rest do stage-1 attention
// =====================================================================================
__global__ __launch_bounds__(256) void k_att_sortadj(const int* __restrict__ rf,
                                                     const int* __restrict__ adj, int N) {
    int nbSort = (N + 7) / 8;
    int wid = threadIdx.x >> 5;
    int lane = threadIdx.x & 31;

    if ((int)blockIdx.x < nbSort) {
        // ---- sortadj: pre-sort each adj row by (la_s desc, position asc) ----
        int gw = blockIdx.x * 8 + wid;
        if (gw >= N) return;
        int b = adj[(size_t)gw * RR + lane];
        unsigned sk = (b == N - 1) ? 0u : ordu(g_las[b]);   // masked strictly below all real
        unsigned long long e = ((unsigned long long)sk << 32)
                             | ((unsigned long long)(unsigned)(31 - lane) << 26)
                             | (unsigned)b;
        e = warp_sort_desc(e, lane);
        g_adjsorted[(size_t)gw * RR + lane] = e;
        return;
    }

    // ---- att: 2 warps per row; both compute att/sort, each gathers half of FO ----
    int half = wid & 1;
    int n = (blockIdx.x - nbSort) * 4 + (wid >> 1);
    if (n >= N) return;
    int j = rf[(size_t)n * RR + lane];

    const float4* Kp = (const float4*)(g_key + (size_t)n * AA);
    float4 ka = Kp[0], kb = Kp[1], kc = Kp[2], kd = Kp[3];
    const float4* Qp = (const float4*)(g_query + (size_t)j * AA);
    float4 qa = Qp[0], qb = Qp[1], qc = Qp[2], qd = Qp[3];
    float att = 0.f;
    att = fmaf(ka.x, qa.x, att); att = fmaf(ka.y, qa.y, att); att = fmaf(ka.z, qa.z, att); att = fmaf(ka.w, qa.w, att);
    att = fmaf(kb.x, qb.x, att); att = fmaf(kb.y, qb.y, att); att = fmaf(kb.z, qb.z, att); att = fmaf(kb.w, qb.w, att);
    att = fmaf(kc.x, qc.x, att); att = fmaf(kc.y, qc.y, att); att = fmaf(kc.z, qc.z, att); att = fmaf(kc.w, qc.w, att);
    att = fmaf(kd.x, qd.x, att); att = fmaf(kd.y, qd.y, att); att = fmaf(kd.z, qd.z, att); att = fmaf(kd.w, qd.w, att);

    att = (att > 0.f) ? att : 0.2f * att;   // leaky relu
    if (j == N - 1) att = -INFINITY;        // mask (softmax weight exactly 0, same as ref)

    float m = att;
#pragma unroll
    for (int o = 16; o; o >>= 1) m = fmaxf(m, __shfl_xor_sync(~0u, m, o));
    float e = expf(att - m);
    float s = e;
#pragma unroll
    for (int o = 16; o; o >>= 1) s += __shfl_xor_sync(~0u, s, o);
    float p = e / s;

    unsigned long long key = ((unsigned long long)ordu(p) << 32) | (unsigned)(~lane);
    key = warp_sort_desc(key, lane);

    float pv = unordu((unsigned)(key >> 32));
    float p0 = __shfl_sync(~0u, pv, 0);
    float ev = (lane < TK) ? expf(pv - p0) : 0.f;
    float ssum = ev;
#pragma unroll
    for (int o = 16; o; o >>= 1) ssum += __shfl_xor_sync(~0u, ssum, o);
    float wnorm = ev / ssum;

    const float4* H = (const float4*)g_newh;
    int base = half * 32;
    float4 acc = H[(size_t)n * 64 + base + lane];
#pragma unroll
    for (int i = 0; i < TK; i++) {
        unsigned long long ki = __shfl_sync(~0u, key, i);
        int wl = (int)((~(unsigned)ki) & 31u);
        int node = __shfl_sync(~0u, j, wl);
        float wi = __shfl_sync(~0u, wnorm, i);
        float4 v = H[(size_t)node * 64 + base + lane];
        acc.x = fmaf(wi, v.x, acc.x); acc.y = fmaf(wi, v.y, acc.y);
        acc.z = fmaf(wi, v.z, acc.z); acc.w = fmaf(wi, v.w, acc.w);
    }
    ((float4*)g_finalpre)[(size_t)n * 64 + base + lane] = acc;
}

// =====================================================================================
// fused STAGE2 + BNSUM kernel (independent work, complementary bottlenecks):
//   blocks [0, nbS2): stage-2 32-way merge (issue-bound, SDEPTH-staged, speculative preload)
//   blocks [nbS2, nbS2+NBBN): batchnorm sums (memory-latency-bound, 2 cols/thread)
// =====================================================================================
__global__ __launch_bounds__(128, 10) void k_stage2_bnsum(const int* __restrict__ rf,
                                                          float* __restrict__ out2, int N, int write2) {
    __shared__ unsigned long long s[4][RR * SSTR];
    int nbS2 = (N + 3) / 4;

    if ((int)blockIdx.x >= nbS2) {
        // ---- bnsum: f32 accumulators (2 cols x 2 row-chains), f64 only at the atomic ----
        int f = threadIdx.x;                 // column pair: f and f+128
        int bb = blockIdx.x - nbS2;
        int stride = NBBN;
        float sA = 0.f, sB = 0.f, sC = 0.f, sD = 0.f;
        float qA = 0.f, qB = 0.f, qC = 0.f, qD = 0.f;
        int r = bb;
        for (; r + stride < N; r += 2 * stride) {
            float v0 = g_finalpre[(size_t)r * FO + f];
            float v1 = g_finalpre[(size_t)r * FO + f + 128];
            float v2 = g_finalpre[(size_t)(r + stride) * FO + f];
            float v3 = g_finalpre[(size_t)(r + stride) * FO + f + 128];
            sA += v0; qA = fmaf(v0, v0, qA);
            sB += v1; qB = fmaf(v1, v1, qB);
            sC += v2; qC = fmaf(v2, v2, qC);
            sD += v3; qD = fmaf(v3, v3, qD);
        }
        for (; r < N; r += stride) {
            float v0 = g_finalpre[(size_t)r * FO + f];
            float v1 = g_finalpre[(size_t)r * FO + f + 128];
            sA += v0; qA = fmaf(v0, v0, qA);
            sB += v1; qB = fmaf(v1, v1, qB);
        }
        atomicAdd(&g_sum[f], (double)(sA + sC));
        atomicAdd(&g_sum[f + 128], (double)(sB + sD));
        atomicAdd(&g_sumsq[f], (double)(qA + qC));
        atomicAdd(&g_sumsq[f + 128], (double)(qB + qD));
        return;
    }

    // ---- stage2: 32-way merge of pre-sorted adj rows, warp-per-row ----
    // order = (sk desc, global position asc) == lexicographic (hi=sk, lo=1024-pos) max.
    int w = threadIdx.x >> 5, lane = threadIdx.x & 31;
    int n = blockIdx.x * 4 + w;
    if (n >= N) return;
    int rfv = rf[(size_t)n * RR + lane];
    if (write2) out2[(size_t)n * RR + lane] = (float)rfv;  // copy of receptive_field slab

    unsigned long long* sw = s[w];
#pragma unroll
    for (int r = 0; r < RR; r++) {
        int row = __shfl_sync(~0u, rfv, r);
        if (lane < SDEPTH)
            sw[r * SSTR + lane] = g_adjsorted[(size_t)row * RR + lane];   // head of each list
    }
    __syncwarp();

    const unsigned long long* mylist = sw + lane * SSTR;
    const unsigned long long* gml = &g_adjsorted[(size_t)rfv * RR];  // overflow fallback (same data)
    int idx = 0;
    unsigned long long e = mylist[0];
    unsigned long long en = mylist[1];       // speculative next (SDEPTH >= 2)
    int basepos = 1024 - lane * RR;
    int d = 31 - (int)((e >> 26) & 31u);
    unsigned hi = (unsigned)(e >> 32);
    unsigned lo = (unsigned)(basepos - d);

    float* oute = out2 + (size_t)N * RR;
    for (int i = 0; i < RR; i++) {
        unsigned mh = hi;
#pragma unroll
        for (int o = 16; o; o >>= 1) {
            unsigned t = __shfl_xor_sync(~0u, mh, o);
            if (t > mh) mh = t;
        }
        unsigned ball = __ballot_sync(~0u, hi == mh);
        bool win;
        if (__popc(ball) == 1) {
            win = (hi == mh);
        } else {
            unsigned lom = (hi == mh) ? lo : 0u;
#pragma unroll
            for (int o = 16; o; o >>= 1) {
                unsigned t = __shfl_xor_sync(~0u, lom, o);
                if (t > lom) lom = t;
            }
            win = (hi == mh) && (lo == lom);   // lo unique among tied -> exactly one winner
        }
        if (win) {
            if (write2) oute[(size_t)n * RR + i] = (float)(unsigned)(e & 0x3FFFFFFu);
            idx++;
            if (idx < RR) {
                e = en;                          // preloaded: off critical path
                d = 31 - (int)((e >> 26) & 31u);
                hi = (unsigned)(e >> 32);
                lo = (unsigned)(basepos - d);
                int nx = idx + 1;
                if (nx < RR) en = (nx < SDEPTH) ? mylist[nx] : gml[nx];
            } else {
                hi = 0u; lo = 0u;                // exhausted (cannot win mid-loop; safe floor)
            }
        }
    }
}

// ---------------- batchnorm finalize + apply (scale derived per-block from finalized sums) ----------------
__global__ __launch_bounds__(256) void k_bnapply(const float* __restrict__ gamma,
                                                 const float* __restrict__ beta,
                                                 float* __restrict__ out, int N) {
    __shared__ float sc[FO], sh[FO];
    int t = threadIdx.x;
    {
        double mean = g_sum[t] / (double)N;
        double var = g_sumsq[t] / (double)N - mean * mean;
        float inv = rsqrtf((float)var + 1e-5f);
        float scv = gamma[t] * inv;
        sc[t] = scv;
        sh[t] = beta[t] - (float)mean * scv;
    }
    __syncthreads();
    size_t total = (size_t)N * 64;
    for (size_t i = (size_t)blockIdx.x * 256 + t; i < total; i += (size_t)gridDim.x * 256) {
        float4 v = ((const float4*)g_finalpre)[i];
        int c = ((int)(i & 63)) * 4;
        v.x = fmaxf(fmaf(v.x, sc[c + 0], sh[c + 0]), 0.f);
        v.y = fmaxf(fmaf(v.y, sc[c + 1], sh[c + 1]), 0.f);
        v.z = fmaxf(fmaf(v.z, sc[c + 2], sh[c + 2]), 0.f);
        v.w = fmaxf(fmaf(v.w, sc[c + 3], sh[c + 3]), 0.f);
        ((float4*)out)[i] = v;
    }
}

// ---------------- launch ----------------
extern "C" void kernel_launch(void* const* d_in, const int* in_sizes, int n_in,
                              void* d_out, int out_size) {
    const float* x    = (const float*)d_in[0];
    const int*   rf   = (const int*)d_in[1];
    const int*   adj  = (const int*)d_in[2];
    const float* W    = (const float*)d_in[3];
    const float* B    = (const float*)d_in[4];
    const float* Wk   = (const float*)d_in[5];
    const float* Bk   = (const float*)d_in[6];
    const float* Wq   = (const float*)d_in[7];
    const float* Bq   = (const float*)d_in[8];
    const float* la   = (const float*)d_in[9];
    const float* Bla  = (const float*)d_in[11];
    const float* gamma= (const float*)d_in[13];
    const float* beta = (const float*)d_in[14];

    int N = in_sizes[0] / FI;
    if (N > MAXN) return;
    float* out = (float*)d_out;
    long need2 = (long)N * FO + 2L * N * RR;
    int write2 = (out_size >= need2) ? 1 : 0;

    dim3 gg((N + 63) / 64, 5);               // y 0..3: gemm tiles (+las tail), y==4: kq
    k_gemm_kq<<<gg, 128>>>(x, W, B, Wk, Bk, Wq, Bq, la, Bla, N);
    int nbSort = (N + 7) / 8, nbAtt = (N + 3) / 4;
    k_att_sortadj<<<nbSort + nbAtt, 256>>>(rf, adj, N);
    int nbS2 = (N + 3) / 4;
    k_stage2_bnsum<<<nbS2 + NBBN, 128>>>(rf, out + (size_t)N * FO, N, write2);
    k_bnapply<<<640, 256>>>(gamma, beta, out, N);
}

// round 16
// speedup vs baseline: 1.0034x; 1.0034x over previous
#include <cuda_runtime.h>
#include <math.h>
#include <float.h>

#define FI 256
#define FO 256
#define AA 16
#define RR 32
#define TK 16
#define MAXN 20000
#define NBBN 592
#define SDEPTH 12          // staged entries per merge list (overflow -> global fallback)
#define SSTR (SDEPTH + 1)  // smem stride (bank-safe)

// ---------------- static device scratch (no allocations allowed) ----------------
__device__ float g_key[MAXN * AA];
__device__ float g_query[MAXN * AA];
__device__ float g_newh[(size_t)MAXN * FO];
__device__ float g_finalpre[(size_t)MAXN * FO];
__device__ float g_las[MAXN];
__device__ unsigned long long g_adjsorted[(size_t)MAXN * RR];
__device__ double g_sum[FO], g_sumsq[FO];

// monotone float <-> uint mapping (for descending-order max selection)
__device__ __forceinline__ unsigned ordu(float f) {
    unsigned u = __float_as_uint(f);
    return (u & 0x80000000u) ? ~u : (u | 0x80000000u);
}
__device__ __forceinline__ float unordu(unsigned u) {
    return (u & 0x80000000u) ? __uint_as_float(u ^ 0x80000000u) : __uint_as_float(~u);
}

__device__ __forceinline__ void cp16(unsigned dst, const void* src) {
    asm volatile("cp.async.cg.shared.global [%0], [%1], 16;" :: "r"(dst), "l"(src));
}
__device__ __forceinline__ void cp_commit() {
    asm volatile("cp.async.commit_group;");
}
__device__ __forceinline__ void cp_wait0() {
    asm volatile("cp.async.wait_group 0;" ::: "memory");
}

// descending warp bitonic sort of 64-bit keys (unique keys -> deterministic total order)
__device__ __forceinline__ unsigned long long warp_sort_desc(unsigned long long key, int lane) {
#pragma unroll
    for (int size = 2; size <= 32; size <<= 1) {
#pragma unroll
        for (int stride = size >> 1; stride; stride >>= 1) {
            unsigned long long other = __shfl_xor_sync(~0u, key, stride);
            bool down = ((lane & size) == 0);
            bool isUpper = ((lane & stride) != 0);
            bool keepMax = down ^ isUpper;
            unsigned long long mx = key > other ? key : other;
            unsigned long long mn = key > other ? other : key;
            key = keepMax ? mx : mn;
        }
    }
    return key;
}

// =====================================================================================
// fused GEMM + KQ kernel: blockIdx.y in [0,4) -> new_h tile; blockIdx.y == 4 -> K/Q tile
// =====================================================================================

// ---- KQ part: 64x32 tile (cols = [Key(16) | Query(16)]); K/Q rounding is tolerance-safe ----
__device__ __forceinline__ void kq_body(char* smraw, int bx,
                                        const float* __restrict__ x,
                                        const float* __restrict__ Wk, const float* __restrict__ Bk,
                                        const float* __restrict__ Wq, const float* __restrict__ Bq,
                                        int N) {
    float (*As)[64][20] = reinterpret_cast<float (*)[64][20]>(smraw);
    float (*Bs)[16][32] = reinterpret_cast<float (*)[16][32]>(smraw + 2 * 64 * 20 * 4);
    int tid = threadIdx.x;
    int m0 = bx * 64;
    if (bx == 0) {            // fold former k_bnzero launch
        g_sum[tid] = 0.0; g_sum[tid + 128] = 0.0;
        g_sumsq[tid] = 0.0; g_sumsq[tid + 128] = 0.0;
    }
    int tx = tid & 7, ty = tid >> 3;

    int ca0 = tid * 2, ca1 = tid * 2 + 1;
    int arow0 = ca0 >> 2, ac40 = ca0 & 3;
    int arow1 = ca1 >> 2, ac41 = ca1 & 3;
    int ag0 = m0 + arow0; if (ag0 > N - 1) ag0 = N - 1;
    int ag1 = m0 + arow1; if (ag1 > N - 1) ag1 = N - 1;
    const float* asrc0 = x + (size_t)ag0 * FI + ac40 * 4;
    const float* asrc1 = x + (size_t)ag1 * FI + ac41 * 4;
    unsigned adst00 = (unsigned)__cvta_generic_to_shared(&As[0][arow0][ac40 * 4]);
    unsigned adst01 = (unsigned)__cvta_generic_to_shared(&As[0][arow1][ac41 * 4]);
    unsigned adst10 = (unsigned)__cvta_generic_to_shared(&As[1][arow0][ac40 * 4]);
    unsigned adst11 = (unsigned)__cvta_generic_to_shared(&As[1][arow1][ac41 * 4]);

    int brr = tid >> 3, bcc = tid & 7;  // row, chunk (0-3: Wk, 4-7: Wq)
    const float* bsrc = (bcc < 4) ? (Wk + (size_t)brr * AA + bcc * 4)
                                  : (Wq + (size_t)brr * AA + (bcc - 4) * 4);
    int bcol = (bcc < 4) ? bcc * 4 : 16 + (bcc - 4) * 4;
    unsigned bdst0 = (unsigned)__cvta_generic_to_shared(&Bs[0][brr][bcol]);
    unsigned bdst1 = (unsigned)__cvta_generic_to_shared(&Bs[1][brr][bcol]);

    float acc[4][4];
#pragma unroll
    for (int i = 0; i < 4; i++)
#pragma unroll
        for (int j = 0; j < 4; j++) acc[i][j] = 0.f;

    cp16(adst00, asrc0);
    cp16(adst01, asrc1);
    cp16(bdst0, bsrc);
    cp_commit();

    for (int s = 0; s < FI / 16; s++) {
        cp_wait0();
        __syncthreads();
        if (s + 1 < FI / 16) {
            int k0n = (s + 1) * 16;
            if (((s + 1) & 1) == 0) {
                cp16(adst00, asrc0 + k0n);
                cp16(adst01, asrc1 + k0n);
                cp16(bdst0, bsrc + (size_t)k0n * AA);
            } else {
                cp16(adst10, asrc0 + k0n);
                cp16(adst11, asrc1 + k0n);
                cp16(bdst1, bsrc + (size_t)k0n * AA);
            }
            cp_commit();
        }
        int bf = s & 1;
#pragma unroll
        for (int kk = 0; kk < 16; kk++) {
            float a0 = As[bf][ty * 4 + 0][kk];
            float a1 = As[bf][ty * 4 + 1][kk];
            float a2 = As[bf][ty * 4 + 2][kk];
            float a3 = As[bf][ty * 4 + 3][kk];
            float4 b = *(const float4*)&Bs[bf][kk][tx * 4];
            acc[0][0] = fmaf(a0, b.x, acc[0][0]); acc[0][1] = fmaf(a0, b.y, acc[0][1]);
            acc[0][2] = fmaf(a0, b.z, acc[0][2]); acc[0][3] = fmaf(a0, b.w, acc[0][3]);
            acc[1][0] = fmaf(a1, b.x, acc[1][0]); acc[1][1] = fmaf(a1, b.y, acc[1][1]);
            acc[1][2] = fmaf(a1, b.z, acc[1][2]); acc[1][3] = fmaf(a1, b.w, acc[1][3]);
            acc[2][0] = fmaf(a2, b.x, acc[2][0]); acc[2][1] = fmaf(a2, b.y, acc[2][1]);
            acc[2][2] = fmaf(a2, b.z, acc[2][2]); acc[2][3] = fmaf(a2, b.w, acc[2][3]);
            acc[3][0] = fmaf(a3, b.x, acc[3][0]); acc[3][1] = fmaf(a3, b.y, acc[3][1]);
            acc[3][2] = fmaf(a3, b.z, acc[3][2]); acc[3][3] = fmaf(a3, b.w, acc[3][3]);
        }
        __syncthreads();
    }
    int c0 = tx * 4;
#pragma unroll
    for (int i = 0; i < 4; i++) {
        int gr = m0 + ty * 4 + i;
        if (gr < N) {
            float4 v;
            if (tx < 4) {
                v.x = acc[i][0] + Bk[c0 + 0]; v.y = acc[i][1] + Bk[c0 + 1];
                v.z = acc[i][2] + Bk[c0 + 2]; v.w = acc[i][3] + Bk[c0 + 3];
                *(float4*)(g_key + (size_t)gr * AA + c0) = v;
            } else {
                int c = c0 - 16;
                v.x = acc[i][0] + Bq[c + 0]; v.y = acc[i][1] + Bq[c + 1];
                v.z = acc[i][2] + Bq[c + 2]; v.w = acc[i][3] + Bq[c + 3];
                *(float4*)(g_query + (size_t)gr * AA + c) = v;
            }
        }
    }
}

// ---- GEMM part: 64x64 tile, 4x8 micro. Ascending-k FMA chain per element + bias at end:
//      rounding structure MUST stay (la_s bit-match depends on newh bits). ----
__global__ __launch_bounds__(128, 8) void k_gemm_kq(const float* __restrict__ x,
                                                    const float* __restrict__ W,
                                                    const float* __restrict__ B,
                                                    const float* __restrict__ Wk, const float* __restrict__ Bk,
                                                    const float* __restrict__ Wq, const float* __restrict__ Bq,
                                                    int N) {
    __shared__ __align__(16) char smraw[2 * 64 * 20 * 4 + 2 * 16 * 64 * 4];
    if (blockIdx.y == 4) {
        kq_body(smraw, blockIdx.x, x, Wk, Bk, Wq, Bq, N);
        return;
    }
    float (*As)[64][20] = reinterpret_cast<float (*)[64][20]>(smraw);
    float (*Bs)[16][64] = reinterpret_cast<float (*)[16][64]>(smraw + 2 * 64 * 20 * 4);
    int tid = threadIdx.x;
    int m0 = blockIdx.x * 64;
    int n0 = blockIdx.y * 64;
    int tx = tid & 7, ty = tid >> 3;

    int ca0 = tid * 2, ca1 = tid * 2 + 1;
    int arow0 = ca0 >> 2, ac40 = ca0 & 3;
    int arow1 = ca1 >> 2, ac41 = ca1 & 3;
    int ag0 = m0 + arow0; if (ag0 > N - 1) ag0 = N - 1;
    int ag1 = m0 + arow1; if (ag1 > N - 1) ag1 = N - 1;
    const float* asrc0 = x + (size_t)ag0 * FI + ac40 * 4;
    const float* asrc1 = x + (size_t)ag1 * FI + ac41 * 4;
    unsigned adst00 = (unsigned)__cvta_generic_to_shared(&As[0][arow0][ac40 * 4]);
    unsigned adst01 = (unsigned)__cvta_generic_to_shared(&As[0][arow1][ac41 * 4]);
    unsigned adst10 = (unsigned)__cvta_generic_to_shared(&As[1][arow0][ac40 * 4]);
    unsigned adst11 = (unsigned)__cvta_generic_to_shared(&As[1][arow1][ac41 * 4]);

    int f0 = tid * 2, f1 = tid * 2 + 1;
    int br0 = f0 >> 4, bc0 = (f0 & 15) * 4;
    int br1 = f1 >> 4, bc1 = (f1 & 15) * 4;
    const float* bsrc0 = W + (size_t)br0 * FO + n0 + bc0;
    const float* bsrc1 = W + (size_t)br1 * FO + n0 + bc1;
    unsigned bdst00 = (unsigned)__cvta_generic_to_shared(&Bs[0][br0][bc0]);
    unsigned bdst01 = (unsigned)__cvta_generic_to_shared(&Bs[0][br1][bc1]);
    unsigned bdst10 = (unsigned)__cvta_generic_to_shared(&Bs[1][br0][bc0]);
    unsigned bdst11 = (unsigned)__cvta_generic_to_shared(&Bs[1][br1][bc1]);

    float acc[4][8];
#pragma unroll
    for (int i = 0; i < 4; i++)
#pragma unroll
        for (int j = 0; j < 8; j++) acc[i][j] = 0.f;

    cp16(adst00, asrc0);
    cp16(adst01, asrc1);
    cp16(bdst00, bsrc0);
    cp16(bdst01, bsrc1);
    cp_commit();

    for (int s = 0; s < FI / 16; s++) {
        cp_wait0();
        __syncthreads();
        if (s + 1 < FI / 16) {
            int k0n = (s + 1) * 16;
            if (((s + 1) & 1) == 0) {
                cp16(adst00, asrc0 + k0n);
                cp16(adst01, asrc1 + k0n);
                cp16(bdst00, bsrc0 + (size_t)k0n * FO);
                cp16(bdst01, bsrc1 + (size_t)k0n * FO);
            } else {
                cp16(adst10, asrc0 + k0n);
                cp16(adst11, asrc1 + k0n);
                cp16(bdst10, bsrc0 + (size_t)k0n * FO);
                cp16(bdst11, bsrc1 + (size_t)k0n * FO);
            }
            cp_commit();
        }
        int bf = s & 1;
#pragma unroll
        for (int kk = 0; kk < 16; kk++) {
            float a0 = As[bf][ty * 4 + 0][kk];
            float a1 = As[bf][ty * 4 + 1][kk];
            float a2 = As[bf][ty * 4 + 2][kk];
            float a3 = As[bf][ty * 4 + 3][kk];
            float4 blo = *(const float4*)&Bs[bf][kk][tx * 4];
            float4 bhi = *(const float4*)&Bs[bf][kk][32 + tx * 4];
            acc[0][0] = fmaf(a0, blo.x, acc[0][0]); acc[0][1] = fmaf(a0, blo.y, acc[0][1]);
            acc[0][2] = fmaf(a0, blo.z, acc[0][2]); acc[0][3] = fmaf(a0, blo.w, acc[0][3]);
            acc[0][4] = fmaf(a0, bhi.x, acc[0][4]); acc[0][5] = fmaf(a0, bhi.y, acc[0][5]);
            acc[0][6] = fmaf(a0, bhi.z, acc[0][6]); acc[0][7] = fmaf(a0, bhi.w, acc[0][7]);
            acc[1][0] = fmaf(a1, blo.x, acc[1][0]); acc[1][1] = fmaf(a1, blo.y, acc[1][1]);
            acc[1][2] = fmaf(a1, blo.z, acc[1][2]); acc[1][3] = fmaf(a1, blo.w, acc[1][3]);
            acc[1][4] = fmaf(a1, bhi.x, acc[1][4]); acc[1][5] = fmaf(a1, bhi.y, acc[1][5]);
            acc[1][6] = fmaf(a1, bhi.z, acc[1][6]); acc[1][7] = fmaf(a1, bhi.w, acc[1][7]);
            acc[2][0] = fmaf(a2, blo.x, acc[2][0]); acc[2][1] = fmaf(a2, blo.y, acc[2][1]);
            acc[2][2] = fmaf(a2, blo.z, acc[2][2]); acc[2][3] = fmaf(a2, blo.w, acc[2][3]);
            acc[2][4] = fmaf(a2, bhi.x, acc[2][4]); acc[2][5] = fmaf(a2, bhi.y, acc[2][5]);
            acc[2][6] = fmaf(a2, bhi.z, acc[2][6]); acc[2][7] = fmaf(a2, bhi.w, acc[2][7]);
            acc[3][0] = fmaf(a3, blo.x, acc[3][0]); acc[3][1] = fmaf(a3, blo.y, acc[3][1]);
            acc[3][2] = fmaf(a3, blo.z, acc[3][2]); acc[3][3] = fmaf(a3, blo.w, acc[3][3]);
            acc[3][4] = fmaf(a3, bhi.x, acc[3][4]); acc[3][5] = fmaf(a3, bhi.y, acc[3][5]);
            acc[3][6] = fmaf(a3, bhi.z, acc[3][6]); acc[3][7] = fmaf(a3, bhi.w, acc[3][7]);
        }
    }
#pragma unroll
    for (int i = 0; i < 4; i++) {
        int gr = m0 + ty * 4 + i;
        if (gr < N) {
            int gc = n0 + tx * 4;
            float4 v0;
            v0.x = acc[i][0] + B[gc + 0]; v0.y = acc[i][1] + B[gc + 1];
            v0.z = acc[i][2] + B[gc + 2]; v0.w = acc[i][3] + B[gc + 3];
            *(float4*)(g_newh + (size_t)gr * FO + gc) = v0;
            int gc2 = n0 + 32 + tx * 4;
            float4 v1;
            v1.x = acc[i][4] + B[gc2 + 0]; v1.y = acc[i][5] + B[gc2 + 1];
            v1.z = acc[i][6] + B[gc2 + 2]; v1.w = acc[i][7] + B[gc2 + 3];
            *(float4*)(g_newh + (size_t)gr * FO + gc2) = v1;
        }
    }
}

// ---------------- la_s: NEON-gemv order, 4 threads/row phase decomposition ----------------
// Thread p accumulates v[4j+p]*la[4j+p] ascending (== NEON lane-p chain); combine
// ((p0+p1)+(p2+p3)) then +Bla — bitwise identical to the proven sequential version.
__global__ __launch_bounds__(256) void k_las(const float* __restrict__ la,
                                             const float* __restrict__ Bla, int N) {
    __shared__ float sla[FO];
    int t = threadIdx.x;
    sla[t] = la[t];
    __syncthreads();
    int rown = blockIdx.x * 64 + (t >> 2);
    int row = rown < N ? rown : N - 1;      // clamp: keep all lanes active for shfl
    int p = t & 3;
    const float* h = g_newh + (size_t)row * FO + p;
    float a = 0.f;
#pragma unroll 16
    for (int j = 0; j < 64; j++)
        a = fmaf(h[4 * j], sla[4 * j + p], a);
    float o1 = __shfl_down_sync(~0u, a, 1);
    float t01 = __fadd_rn(a, o1);            // p0: a0+a1 ; p2: a2+a3
    float t23 = __shfl_down_sync(~0u, t01, 2);
    if (rown < N && p == 0)
        g_las[row] = __fadd_rn(t01, t23) + Bla[0];
}

// =====================================================================================
// fused ATT + SORTADJ kernel: blocks [0, nbSort) sort adj rows; rest do stage-1 attention
// =====================================================================================
__global__ __launch_bounds__(256) void k_att_sortadj(const int* __restrict__ rf,
                                                     const int* __restrict__ adj, int N) {
    int nbSort = (N + 7) / 8;
    int wid = threadIdx.x >> 5;
    int lane = threadIdx.x & 31;

    if ((int)blockIdx.x < nbSort) {
        // ---- sortadj: pre-sort each adj row by (la_s desc, position asc) ----
        int gw = blockIdx.x * 8 + wid;
        if (gw >= N) return;
        int b = adj[(size_t)gw * RR + lane];
        unsigned sk = (b == N - 1) ? 0u : ordu(g_las[b]);   // masked strictly below all real
        unsigned long long e = ((unsigned long long)sk << 32)
                             | ((unsigned long long)(unsigned)(31 - lane) << 26)
                             | (unsigned)b;
        e = warp_sort_desc(e, lane);
        g_adjsorted[(size_t)gw * RR + lane] = e;
        return;
    }

    // ---- att: 2 warps per row; both compute att/sort, each gathers half of FO ----
    int half = wid & 1;
    int n = (blockIdx.x - nbSort) * 4 + (wid >> 1);
    if (n >= N) return;
    int j = rf[(size_t)n * RR + lane];

    const float4* Kp = (const float4*)(g_key + (size_t)n * AA);
    float4 ka = Kp[0], kb = Kp[1], kc = Kp[2], kd = Kp[3];
    const float4* Qp = (const float4*)(g_query + (size_t)j * AA);
    float4 qa = Qp[0], qb = Qp[1], qc = Qp[2], qd = Qp[3];
    float att = 0.f;
    att = fmaf(ka.x, qa.x, att); att = fmaf(ka.y, qa.y, att); att = fmaf(ka.z, qa.z, att); att = fmaf(ka.w, qa.w, att);
    att = fmaf(kb.x, qb.x, att); att = fmaf(kb.y, qb.y, att); att = fmaf(kb.z, qb.z, att); att = fmaf(kb.w, qb.w, att);
    att = fmaf(kc.x, qc.x, att); att = fmaf(kc.y, qc.y, att); att = fmaf(kc.z, qc.z, att); att = fmaf(kc.w, qc.w, att);
    att = fmaf(kd.x, qd.x, att); att = fmaf(kd.y, qd.y, att); att = fmaf(kd.z, qd.z, att); att = fmaf(kd.w, qd.w, att);

    att = (att > 0.f) ? att : 0.2f * att;   // leaky relu
    if (j == N - 1) att = -INFINITY;        // mask (softmax weight exactly 0, same as ref)

    float m = att;
#pragma unroll
    for (int o = 16; o; o >>= 1) m = fmaxf(m, __shfl_xor_sync(~0u, m, o));
    float e = expf(att - m);
    float s = e;
#pragma unroll
    for (int o = 16; o; o >>= 1) s += __shfl_xor_sync(~0u, s, o);
    float p = e / s;

    unsigned long long key = ((unsigned long long)ordu(p) << 32) | (unsigned)(~lane);
    key = warp_sort_desc(key, lane);

    float pv = unordu((unsigned)(key >> 32));
    float p0 = __shfl_sync(~0u, pv, 0);
    float ev = (lane < TK) ? expf(pv - p0) : 0.f;
    float ssum = ev;
#pragma unroll
    for (int o = 16; o; o >>= 1) ssum += __shfl_xor_sync(~0u, ssum, o);
    float wnorm = ev / ssum;

    const float4* H = (const float4*)g_newh;
    int base = half * 32;
    float4 acc = H[(size_t)n * 64 + base + lane];
#pragma unroll
    for (int i = 0; i < TK; i++) {
        unsigned long long ki = __shfl_sync(~0u, key, i);
        int wl = (int)((~(unsigned)ki) & 31u);
        int node = __shfl_sync(~0u, j, wl);
        float wi = __shfl_sync(~0u, wnorm, i);
        float4 v = H[(size_t)node * 64 + base + lane];
        acc.x = fmaf(wi, v.x, acc.x); acc.y = fmaf(wi, v.y, acc.y);
        acc.z = fmaf(wi, v.z, acc.z); acc.w = fmaf(wi, v.w, acc.w);
    }
    ((float4*)g_finalpre)[(size_t)n * 64 + base + lane] = acc;
}

// =====================================================================================
// fused STAGE2 + BNSUM kernel (independent work, complementary bottlenecks):
//   blocks [0, nbS2): stage-2 32-way merge (shfl/issue-bound, SDEPTH-staged lists)
//   blocks [nbS2, nbS2+NBBN): batchnorm sums (memory-latency-bound, 2 cols/thread)
// =====================================================================================
__global__ __launch_bounds__(128, 10) void k_stage2_bnsum(const int* __restrict__ rf,
                                                          float* __restrict__ out2, int N, int write2) {
    __shared__ unsigned long long s[4][RR * SSTR];
    int nbS2 = (N + 3) / 4;

    if ((int)blockIdx.x >= nbS2) {
        // ---- bnsum: f32 accumulators (2 cols x 2 row-chains), f64 only at the atomic ----
        int f = threadIdx.x;                 // column pair: f and f+128
        int bb = blockIdx.x - nbS2;
        int stride = NBBN;
        float sA = 0.f, sB = 0.f, sC = 0.f, sD = 0.f;
        float qA = 0.f, qB = 0.f, qC = 0.f, qD = 0.f;
        int r = bb;
        for (; r + stride < N; r += 2 * stride) {
            float v0 = g_finalpre[(size_t)r * FO + f];
            float v1 = g_finalpre[(size_t)r * FO + f + 128];
            float v2 = g_finalpre[(size_t)(r + stride) * FO + f];
            float v3 = g_finalpre[(size_t)(r + stride) * FO + f + 128];
            sA += v0; qA = fmaf(v0, v0, qA);
            sB += v1; qB = fmaf(v1, v1, qB);
            sC += v2; qC = fmaf(v2, v2, qC);
            sD += v3; qD = fmaf(v3, v3, qD);
        }
        for (; r < N; r += stride) {
            float v0 = g_finalpre[(size_t)r * FO + f];
            float v1 = g_finalpre[(size_t)r * FO + f + 128];
            sA += v0; qA = fmaf(v0, v0, qA);
            sB += v1; qB = fmaf(v1, v1, qB);
        }
        atomicAdd(&g_sum[f], (double)(sA + sC));
        atomicAdd(&g_sum[f + 128], (double)(sB + sD));
        atomicAdd(&g_sumsq[f], (double)(qA + qC));
        atomicAdd(&g_sumsq[f + 128], (double)(qB + qD));
        return;
    }

    // ---- stage2: 32-way merge of pre-sorted adj rows, warp-per-row ----
    // order = (sk desc, global position asc) == lexicographic (hi=sk, lo=1024-pos) max.
    int w = threadIdx.x >> 5, lane = threadIdx.x & 31;
    int n = blockIdx.x * 4 + w;
    if (n >= N) return;
    int rfv = rf[(size_t)n * RR + lane];
    if (write2) out2[(size_t)n * RR + lane] = (float)rfv;  // copy of receptive_field slab

    unsigned long long* sw = s[w];
#pragma unroll
    for (int r = 0; r < RR; r++) {
        int row = __shfl_sync(~0u, rfv, r);
        if (lane < SDEPTH)
            sw[r * SSTR + lane] = g_adjsorted[(size_t)row * RR + lane];   // head of each list
    }
    __syncwarp();

    const unsigned long long* mylist = sw + lane * SSTR;
    const unsigned long long* gml = &g_adjsorted[(size_t)rfv * RR];  // overflow fallback (same data)
    int idx = 0;
    unsigned long long e = mylist[0];
    int basepos = 1024 - lane * RR;
    int d = 31 - (int)((e >> 26) & 31u);
    unsigned hi = (unsigned)(e >> 32);
    unsigned lo = (unsigned)(basepos - d);

    float* oute = out2 + (size_t)N * RR;
    for (int i = 0; i < RR; i++) {
        unsigned mh = hi;
#pragma unroll
        for (int o = 16; o; o >>= 1) {
            unsigned t = __shfl_xor_sync(~0u, mh, o);
            if (t > mh) mh = t;
        }
        unsigned ball = __ballot_sync(~0u, hi == mh);
        bool win;
        if (__popc(ball) == 1) {
            win = (hi == mh);
        } else {
            unsigned lom = (hi == mh) ? lo : 0u;
#pragma unroll
            for (int o = 16; o; o >>= 1) {
                unsigned t = __shfl_xor_sync(~0u, lom, o);
                if (t > lom) lom = t;
            }
            win = (hi == mh) && (lo == lom);   // lo unique among tied -> exactly one winner
        }
        if (win) {
            if (write2) oute[(size_t)n * RR + i] = (float)(unsigned)(e & 0x3FFFFFFu);
            idx++;
            if (idx < RR) {
                e = (idx < SDEPTH) ? mylist[idx] : gml[idx];   // rare overflow -> L2 (identical bits)
                d = 31 - (int)((e >> 26) & 31u);
                hi = (unsigned)(e >> 32);
                lo = (unsigned)(basepos - d);
            } else {
                hi = 0u; lo = 0u;              // exhausted (cannot win mid-loop; safe floor)
            }
        }
    }
}

// ---------------- batchnorm finalize + apply: full residency + 2-way unrolled stream ----------------
__global__ __launch_bounds__(256) void k_bnapply(const float* __restrict__ gamma,
                                                 const float* __restrict__ beta,
                                                 float* __restrict__ out, int N) {
    __shared__ float sc[FO], sh[FO];
    int t = threadIdx.x;
    {
        double mean = g_sum[t] / (double)N;
        double var = g_sumsq[t] / (double)N - mean * mean;
        float inv = rsqrtf((float)var + 1e-5f);
        float scv = gamma[t] * inv;
        sc[t] = scv;
        sh[t] = beta[t] - (float)mean * scv;
    }
    __syncthreads();
    size_t total = (size_t)N * 64;
    size_t step = (size_t)gridDim.x * 256;
    size_t i = (size_t)blockIdx.x * 256 + t;
    for (; i + step < total; i += 2 * step) {
        float4 v0 = ((const float4*)g_finalpre)[i];
        float4 v1 = ((const float4*)g_finalpre)[i + step];
        int c0 = ((int)(i & 63)) * 4;
        int c1 = ((int)((i + step) & 63)) * 4;
        v0.x = fmaxf(fmaf(v0.x, sc[c0 + 0], sh[c0 + 0]), 0.f);
        v0.y = fmaxf(fmaf(v0.y, sc[c0 + 1], sh[c0 + 1]), 0.f);
        v0.z = fmaxf(fmaf(v0.z, sc[c0 + 2], sh[c0 + 2]), 0.f);
        v0.w = fmaxf(fmaf(v0.w, sc[c0 + 3], sh[c0 + 3]), 0.f);
        v1.x = fmaxf(fmaf(v1.x, sc[c1 + 0], sh[c1 + 0]), 0.f);
        v1.y = fmaxf(fmaf(v1.y, sc[c1 + 1], sh[c1 + 1]), 0.f);
        v1.z = fmaxf(fmaf(v1.z, sc[c1 + 2], sh[c1 + 2]), 0.f);
        v1.w = fmaxf(fmaf(v1.w, sc[c1 + 3], sh[c1 + 3]), 0.f);
        ((float4*)out)[i] = v0;
        ((float4*)out)[i + step] = v1;
    }
    for (; i < total; i += step) {
        float4 v = ((const float4*)g_finalpre)[i];
        int c = ((int)(i & 63)) * 4;
        v.x = fmaxf(fmaf(v.x, sc[c + 0], sh[c + 0]), 0.f);
        v.y = fmaxf(fmaf(v.y, sc[c + 1], sh[c + 1]), 0.f);
        v.z = fmaxf(fmaf(v.z, sc[c + 2], sh[c + 2]), 0.f);
        v.w = fmaxf(fmaf(v.w, sc[c + 3], sh[c + 3]), 0.f);
        ((float4*)out)[i] = v;
    }
}

// ---------------- launch ----------------
extern "C" void kernel_launch(void* const* d_in, const int* in_sizes, int n_in,
                              void* d_out, int out_size) {
    const float* x    = (const float*)d_in[0];
    const int*   rf   = (const int*)d_in[1];
    const int*   adj  = (const int*)d_in[2];
    const float* W    = (const float*)d_in[3];
    const float* B    = (const float*)d_in[4];
    const float* Wk   = (const float*)d_in[5];
    const float* Bk   = (const float*)d_in[6];
    const float* Wq   = (const float*)d_in[7];
    const float* Bq   = (const float*)d_in[8];
    const float* la   = (const float*)d_in[9];
    const float* Bla  = (const float*)d_in[11];
    const float* gamma= (const float*)d_in[13];
    const float* beta = (const float*)d_in[14];

    int N = in_sizes[0] / FI;
    if (N > MAXN) return;
    float* out = (float*)d_out;
    long need2 = (long)N * FO + 2L * N * RR;
    int write2 = (out_size >= need2) ? 1 : 0;

    dim3 gg((N + 63) / 64, 5);               // y 0..3: gemm tiles, y==4: kq
    k_gemm_kq<<<gg, 128>>>(x, W, B, Wk, Bk, Wq, Bq, N);
    k_las<<<(N + 63) / 64, 256>>>(la, Bla, N);
    int nbSort = (N + 7) / 8, nbAtt = (N + 3) / 4;
    k_att_sortadj<<<nbSort + nbAtt, 256>>>(rf, adj, N);
    int nbS2 = (N + 3) / 4;
    k_stage2_bnsum<<<nbS2 + NBBN, 128>>>(rf, out + (size_t)N * FO, N, write2);
    k_bnapply<<<1184, 256>>>(gamma, beta, out, N);
}

// round 17
// speedup vs baseline: 1.0425x; 1.0390x over previous
#include <cuda_runtime.h>
#include <math.h>
#include <float.h>

#define FI 256
#define FO 256
#define AA 16
#define RR 32
#define TK 16
#define MAXN 20000
#define NBBN 592
#define SDEPTH 12          // staged entries per merge list (overflow -> global fallback)
#define SSTR (SDEPTH + 1)  // smem stride (bank-safe)

// ---------------- static device scratch (no allocations allowed) ----------------
__device__ float g_key[MAXN * AA];
__device__ float g_query[MAXN * AA];
__device__ float g_newh[(size_t)MAXN * FO];
__device__ float g_finalpre[(size_t)MAXN * FO];
__device__ float g_las[MAXN];
__device__ unsigned long long g_adjsorted[(size_t)MAXN * RR];
__device__ double g_sum[FO], g_sumsq[FO];

// monotone float <-> uint mapping (for descending-order max selection)
__device__ __forceinline__ unsigned ordu(float f) {
    unsigned u = __float_as_uint(f);
    return (u & 0x80000000u) ? ~u : (u | 0x80000000u);
}
__device__ __forceinline__ float unordu(unsigned u) {
    return (u & 0x80000000u) ? __uint_as_float(u ^ 0x80000000u) : __uint_as_float(~u);
}

__device__ __forceinline__ void cp16(unsigned dst, const void* src) {
    asm volatile("cp.async.cg.shared.global [%0], [%1], 16;" :: "r"(dst), "l"(src));
}
__device__ __forceinline__ void cp_commit() {
    asm volatile("cp.async.commit_group;");
}
__device__ __forceinline__ void cp_wait0() {
    asm volatile("cp.async.wait_group 0;" ::: "memory");
}

// descending warp bitonic sort of 64-bit keys (unique keys -> deterministic total order)
__device__ __forceinline__ unsigned long long warp_sort_desc(unsigned long long key, int lane) {
#pragma unroll
    for (int size = 2; size <= 32; size <<= 1) {
#pragma unroll
        for (int stride = size >> 1; stride; stride >>= 1) {
            unsigned long long other = __shfl_xor_sync(~0u, key, stride);
            bool down = ((lane & size) == 0);
            bool isUpper = ((lane & stride) != 0);
            bool keepMax = down ^ isUpper;
            unsigned long long mx = key > other ? key : other;
            unsigned long long mn = key > other ? other : key;
            key = keepMax ? mx : mn;
        }
    }
    return key;
}

// =====================================================================================
// fused GEMM + KQ kernel: blockIdx.y in [0,4) -> new_h tile; blockIdx.y == 4 -> K/Q tile
// =====================================================================================

// ---- KQ part: 64x32 tile (cols = [Key(16) | Query(16)]); K/Q rounding is tolerance-safe ----
__device__ __forceinline__ void kq_body(char* smraw, int bx,
                                        const float* __restrict__ x,
                                        const float* __restrict__ Wk, const float* __restrict__ Bk,
                                        const float* __restrict__ Wq, const float* __restrict__ Bq,
                                        int N) {
    float (*As)[64][20] = reinterpret_cast<float (*)[64][20]>(smraw);
    float (*Bs)[16][32] = reinterpret_cast<float (*)[16][32]>(smraw + 2 * 64 * 20 * 4);
    int tid = threadIdx.x;
    int m0 = bx * 64;
    if (bx == 0) {            // fold former k_bnzero launch
        g_sum[tid] = 0.0; g_sum[tid + 128] = 0.0;
        g_sumsq[tid] = 0.0; g_sumsq[tid + 128] = 0.0;
    }
    int tx = tid & 7, ty = tid >> 3;

    int ca0 = tid * 2, ca1 = tid * 2 + 1;
    int arow0 = ca0 >> 2, ac40 = ca0 & 3;
    int arow1 = ca1 >> 2, ac41 = ca1 & 3;
    int ag0 = m0 + arow0; if (ag0 > N - 1) ag0 = N - 1;
    int ag1 = m0 + arow1; if (ag1 > N - 1) ag1 = N - 1;
    const float* asrc0 = x + (size_t)ag0 * FI + ac40 * 4;
    const float* asrc1 = x + (size_t)ag1 * FI + ac41 * 4;
    unsigned adst00 = (unsigned)__cvta_generic_to_shared(&As[0][arow0][ac40 * 4]);
    unsigned adst01 = (unsigned)__cvta_generic_to_shared(&As[0][arow1][ac41 * 4]);
    unsigned adst10 = (unsigned)__cvta_generic_to_shared(&As[1][arow0][ac40 * 4]);
    unsigned adst11 = (unsigned)__cvta_generic_to_shared(&As[1][arow1][ac41 * 4]);

    int brr = tid >> 3, bcc = tid & 7;  // row, chunk (0-3: Wk, 4-7: Wq)
    const float* bsrc = (bcc < 4) ? (Wk + (size_t)brr * AA + bcc * 4)
                                  : (Wq + (size_t)brr * AA + (bcc - 4) * 4);
    int bcol = (bcc < 4) ? bcc * 4 : 16 + (bcc - 4) * 4;
    unsigned bdst0 = (unsigned)__cvta_generic_to_shared(&Bs[0][brr][bcol]);
    unsigned bdst1 = (unsigned)__cvta_generic_to_shared(&Bs[1][brr][bcol]);

    float acc[4][4];
#pragma unroll
    for (int i = 0; i < 4; i++)
#pragma unroll
        for (int j = 0; j < 4; j++) acc[i][j] = 0.f;

    cp16(adst00, asrc0);
    cp16(adst01, asrc1);
    cp16(bdst0, bsrc);
    cp_commit();

    for (int s = 0; s < FI / 16; s++) {
        cp_wait0();
        __syncthreads();
        if (s + 1 < FI / 16) {
            int k0n = (s + 1) * 16;
            if (((s + 1) & 1) == 0) {
                cp16(adst00, asrc0 + k0n);
                cp16(adst01, asrc1 + k0n);
                cp16(bdst0, bsrc + (size_t)k0n * AA);
            } else {
                cp16(adst10, asrc0 + k0n);
                cp16(adst11, asrc1 + k0n);
                cp16(bdst1, bsrc + (size_t)k0n * AA);
            }
            cp_commit();
        }
        int bf = s & 1;
#pragma unroll
        for (int kk = 0; kk < 16; kk++) {
            float a0 = As[bf][ty * 4 + 0][kk];
            float a1 = As[bf][ty * 4 + 1][kk];
            float a2 = As[bf][ty * 4 + 2][kk];
            float a3 = As[bf][ty * 4 + 3][kk];
            float4 b = *(const float4*)&Bs[bf][kk][tx * 4];
            acc[0][0] = fmaf(a0, b.x, acc[0][0]); acc[0][1] = fmaf(a0, b.y, acc[0][1]);
            acc[0][2] = fmaf(a0, b.z, acc[0][2]); acc[0][3] = fmaf(a0, b.w, acc[0][3]);
            acc[1][0] = fmaf(a1, b.x, acc[1][0]); acc[1][1] = fmaf(a1, b.y, acc[1][1]);
            acc[1][2] = fmaf(a1, b.z, acc[1][2]); acc[1][3] = fmaf(a1, b.w, acc[1][3]);
            acc[2][0] = fmaf(a2, b.x, acc[2][0]); acc[2][1] = fmaf(a2, b.y, acc[2][1]);
            acc[2][2] = fmaf(a2, b.z, acc[2][2]); acc[2][3] = fmaf(a2, b.w, acc[2][3]);
            acc[3][0] = fmaf(a3, b.x, acc[3][0]); acc[3][1] = fmaf(a3, b.y, acc[3][1]);
            acc[3][2] = fmaf(a3, b.z, acc[3][2]); acc[3][3] = fmaf(a3, b.w, acc[3][3]);
        }
        __syncthreads();
    }
    int c0 = tx * 4;
#pragma unroll
    for (int i = 0; i < 4; i++) {
        int gr = m0 + ty * 4 + i;
        if (gr < N) {
            float4 v;
            if (tx < 4) {
                v.x = acc[i][0] + Bk[c0 + 0]; v.y = acc[i][1] + Bk[c0 + 1];
                v.z = acc[i][2] + Bk[c0 + 2]; v.w = acc[i][3] + Bk[c0 + 3];
                *(float4*)(g_key + (size_t)gr * AA + c0) = v;
            } else {
                int c = c0 - 16;
                v.x = acc[i][0] + Bq[c + 0]; v.y = acc[i][1] + Bq[c + 1];
                v.z = acc[i][2] + Bq[c + 2]; v.w = acc[i][3] + Bq[c + 3];
                *(float4*)(g_query + (size_t)gr * AA + c) = v;
            }
        }
    }
}

// ---- GEMM part: 64x64 tile, 4x8 micro. Ascending-k FMA chain per element + bias at end:
//      rounding structure MUST stay (la_s bit-match depends on newh bits). ----
__global__ __launch_bounds__(128, 8) void k_gemm_kq(const float* __restrict__ x,
                                                    const float* __restrict__ W,
                                                    const float* __restrict__ B,
                                                    const float* __restrict__ Wk, const float* __restrict__ Bk,
                                                    const float* __restrict__ Wq, const float* __restrict__ Bq,
                                                    int N) {
    __shared__ __align__(16) char smraw[2 * 64 * 20 * 4 + 2 * 16 * 64 * 4];
    if (blockIdx.y == 4) {
        kq_body(smraw, blockIdx.x, x, Wk, Bk, Wq, Bq, N);
        return;
    }
    float (*As)[64][20] = reinterpret_cast<float (*)[64][20]>(smraw);
    float (*Bs)[16][64] = reinterpret_cast<float (*)[16][64]>(smraw + 2 * 64 * 20 * 4);
    int tid = threadIdx.x;
    int m0 = blockIdx.x * 64;
    int n0 = blockIdx.y * 64;
    int tx = tid & 7, ty = tid >> 3;

    int ca0 = tid * 2, ca1 = tid * 2 + 1;
    int arow0 = ca0 >> 2, ac40 = ca0 & 3;
    int arow1 = ca1 >> 2, ac41 = ca1 & 3;
    int ag0 = m0 + arow0; if (ag0 > N - 1) ag0 = N - 1;
    int ag1 = m0 + arow1; if (ag1 > N - 1) ag1 = N - 1;
    const float* asrc0 = x + (size_t)ag0 * FI + ac40 * 4;
    const float* asrc1 = x + (size_t)ag1 * FI + ac41 * 4;
    unsigned adst00 = (unsigned)__cvta_generic_to_shared(&As[0][arow0][ac40 * 4]);
    unsigned adst01 = (unsigned)__cvta_generic_to_shared(&As[0][arow1][ac41 * 4]);
    unsigned adst10 = (unsigned)__cvta_generic_to_shared(&As[1][arow0][ac40 * 4]);
    unsigned adst11 = (unsigned)__cvta_generic_to_shared(&As[1][arow1][ac41 * 4]);

    int f0 = tid * 2, f1 = tid * 2 + 1;
    int br0 = f0 >> 4, bc0 = (f0 & 15) * 4;
    int br1 = f1 >> 4, bc1 = (f1 & 15) * 4;
    const float* bsrc0 = W + (size_t)br0 * FO + n0 + bc0;
    const float* bsrc1 = W + (size_t)br1 * FO + n0 + bc1;
    unsigned bdst00 = (unsigned)__cvta_generic_to_shared(&Bs[0][br0][bc0]);
    unsigned bdst01 = (unsigned)__cvta_generic_to_shared(&Bs[0][br1][bc1]);
    unsigned bdst10 = (unsigned)__cvta_generic_to_shared(&Bs[1][br0][bc0]);
    unsigned bdst11 = (unsigned)__cvta_generic_to_shared(&Bs[1][br1][bc1]);

    float acc[4][8];
#pragma unroll
    for (int i = 0; i < 4; i++)
#pragma unroll
        for (int j = 0; j < 8; j++) acc[i][j] = 0.f;

    cp16(adst00, asrc0);
    cp16(adst01, asrc1);
    cp16(bdst00, bsrc0);
    cp16(bdst01, bsrc1);
    cp_commit();

    for (int s = 0; s < FI / 16; s++) {
        cp_wait0();
        __syncthreads();
        if (s + 1 < FI / 16) {
            int k0n = (s + 1) * 16;
            if (((s + 1) & 1) == 0) {
                cp16(adst00, asrc0 + k0n);
                cp16(adst01, asrc1 + k0n);
                cp16(bdst00, bsrc0 + (size_t)k0n * FO);
                cp16(bdst01, bsrc1 + (size_t)k0n * FO);
            } else {
                cp16(adst10, asrc0 + k0n);
                cp16(adst11, asrc1 + k0n);
                cp16(bdst10, bsrc0 + (size_t)k0n * FO);
                cp16(bdst11, bsrc1 + (size_t)k0n * FO);
            }
            cp_commit();
        }
        int bf = s & 1;
#pragma unroll
        for (int kk = 0; kk < 16; kk++) {
            float a0 = As[bf][ty * 4 + 0][kk];
            float a1 = As[bf][ty * 4 + 1][kk];
            float a2 = As[bf][ty * 4 + 2][kk];
            float a3 = As[bf][ty * 4 + 3][kk];
            float4 blo = *(const float4*)&Bs[bf][kk][tx * 4];
            float4 bhi = *(const float4*)&Bs[bf][kk][32 + tx * 4];
            acc[0][0] = fmaf(a0, blo.x, acc[0][0]); acc[0][1] = fmaf(a0, blo.y, acc[0][1]);
            acc[0][2] = fmaf(a0, blo.z, acc[0][2]); acc[0][3] = fmaf(a0, blo.w, acc[0][3]);
            acc[0][4] = fmaf(a0, bhi.x, acc[0][4]); acc[0][5] = fmaf(a0, bhi.y, acc[0][5]);
            acc[0][6] = fmaf(a0, bhi.z, acc[0][6]); acc[0][7] = fmaf(a0, bhi.w, acc[0][7]);
            acc[1][0] = fmaf(a1, blo.x, acc[1][0]); acc[1][1] = fmaf(a1, blo.y, acc[1][1]);
            acc[1][2] = fmaf(a1, blo.z, acc[1][2]); acc[1][3] = fmaf(a1, blo.w, acc[1][3]);
            acc[1][4] = fmaf(a1, bhi.x, acc[1][4]); acc[1][5] = fmaf(a1, bhi.y, acc[1][5]);
            acc[1][6] = fmaf(a1, bhi.z, acc[1][6]); acc[1][7] = fmaf(a1, bhi.w, acc[1][7]);
            acc[2][0] = fmaf(a2, blo.x, acc[2][0]); acc[2][1] = fmaf(a2, blo.y, acc[2][1]);
            acc[2][2] = fmaf(a2, blo.z, acc[2][2]); acc[2][3] = fmaf(a2, blo.w, acc[2][3]);
            acc[2][4] = fmaf(a2, bhi.x, acc[2][4]); acc[2][5] = fmaf(a2, bhi.y, acc[2][5]);
            acc[2][6] = fmaf(a2, bhi.z, acc[2][6]); acc[2][7] = fmaf(a2, bhi.w, acc[2][7]);
            acc[3][0] = fmaf(a3, blo.x, acc[3][0]); acc[3][1] = fmaf(a3, blo.y, acc[3][1]);
            acc[3][2] = fmaf(a3, blo.z, acc[3][2]); acc[3][3] = fmaf(a3, blo.w, acc[3][3]);
            acc[3][4] = fmaf(a3, bhi.x, acc[3][4]); acc[3][5] = fmaf(a3, bhi.y, acc[3][5]);
            acc[3][6] = fmaf(a3, bhi.z, acc[3][6]); acc[3][7] = fmaf(a3, bhi.w, acc[3][7]);
        }
    }
#pragma unroll
    for (int i = 0; i < 4; i++) {
        int gr = m0 + ty * 4 + i;
        if (gr < N) {
            int gc = n0 + tx * 4;
            float4 v0;
            v0.x = acc[i][0] + B[gc + 0]; v0.y = acc[i][1] + B[gc + 1];
            v0.z = acc[i][2] + B[gc + 2]; v0.w = acc[i][3] + B[gc + 3];
            *(float4*)(g_newh + (size_t)gr * FO + gc) = v0;
            int gc2 = n0 + 32 + tx * 4;
            float4 v1;
            v1.x = acc[i][4] + B[gc2 + 0]; v1.y = acc[i][5] + B[gc2 + 1];
            v1.z = acc[i][6] + B[gc2 + 2]; v1.w = acc[i][7] + B[gc2 + 3];
            *(float4*)(g_newh + (size_t)gr * FO + gc2) = v1;
        }
    }
}

// ---------------- la_s: NEON-gemv order, 4 threads/row phase decomposition ----------------
// Thread p accumulates v[4j+p]*la[4j+p] ascending (== NEON lane-p chain); combine
// ((p0+p1)+(p2+p3)) then +Bla — bitwise identical to the proven sequential version.
__global__ __launch_bounds__(256) void k_las(const float* __restrict__ la,
                                             const float* __restrict__ Bla, int N) {
    __shared__ float sla[FO];
    int t = threadIdx.x;
    sla[t] = la[t];
    __syncthreads();
    int rown = blockIdx.x * 64 + (t >> 2);
    int row = rown < N ? rown : N - 1;      // clamp: keep all lanes active for shfl
    int p = t & 3;
    const float* h = g_newh + (size_t)row * FO + p;
    float a = 0.f;
#pragma unroll 16
    for (int j = 0; j < 64; j++)
        a = fmaf(h[4 * j], sla[4 * j + p], a);
    float o1 = __shfl_down_sync(~0u, a, 1);
    float t01 = __fadd_rn(a, o1);            // p0: a0+a1 ; p2: a2+a3
    float t23 = __shfl_down_sync(~0u, t01, 2);
    if (rown < N && p == 0)
        g_las[row] = __fadd_rn(t01, t23) + Bla[0];
}

// =====================================================================================
// fused ATT + SORTADJ kernel: blocks [0, nbSort) sort adj rows; rest do stage-1 attention
// =====================================================================================
__global__ __launch_bounds__(256) void k_att_sortadj(const int* __restrict__ rf,
                                                     const int* __restrict__ adj, int N) {
    int nbSort = (N + 7) / 8;
    int wid = threadIdx.x >> 5;
    int lane = threadIdx.x & 31;

    if ((int)blockIdx.x < nbSort) {
        // ---- sortadj: pre-sort each adj row by (la_s desc, position asc) ----
        int gw = blockIdx.x * 8 + wid;
        if (gw >= N) return;
        int b = adj[(size_t)gw * RR + lane];
        unsigned sk = (b == N - 1) ? 0u : ordu(g_las[b]);   // masked strictly below all real
        unsigned long long e = ((unsigned long long)sk << 32)
                             | ((unsigned long long)(unsigned)(31 - lane) << 26)
                             | (unsigned)b;
        e = warp_sort_desc(e, lane);
        g_adjsorted[(size_t)gw * RR + lane] = e;
        return;
    }

    // ---- att: 2 warps per row; both compute att/sort, each gathers half of FO ----
    int half = wid & 1;
    int n = (blockIdx.x - nbSort) * 4 + (wid >> 1);
    if (n >= N) return;
    int j = rf[(size_t)n * RR + lane];

    const float4* Kp = (const float4*)(g_key + (size_t)n * AA);
    float4 ka = Kp[0], kb = Kp[1], kc = Kp[2], kd = Kp[3];
    const float4* Qp = (const float4*)(g_query + (size_t)j * AA);
    float4 qa = Qp[0], qb = Qp[1], qc = Qp[2], qd = Qp[3];
    float att = 0.f;
    att = fmaf(ka.x, qa.x, att); att = fmaf(ka.y, qa.y, att); att = fmaf(ka.z, qa.z, att); att = fmaf(ka.w, qa.w, att);
    att = fmaf(kb.x, qb.x, att); att = fmaf(kb.y, qb.y, att); att = fmaf(kb.z, qb.z, att); att = fmaf(kb.w, qb.w, att);
    att = fmaf(kc.x, qc.x, att); att = fmaf(kc.y, qc.y, att); att = fmaf(kc.z, qc.z, att); att = fmaf(kc.w, qc.w, att);
    att = fmaf(kd.x, qd.x, att); att = fmaf(kd.y, qd.y, att); att = fmaf(kd.z, qd.z, att); att = fmaf(kd.w, qd.w, att);

    att = (att > 0.f) ? att : 0.2f * att;   // leaky relu
    if (j == N - 1) att = -INFINITY;        // mask (softmax weight exactly 0, same as ref)

    float m = att;
#pragma unroll
    for (int o = 16; o; o >>= 1) m = fmaxf(m, __shfl_xor_sync(~0u, m, o));
    float e = expf(att - m);
    float s = e;
#pragma unroll
    for (int o = 16; o; o >>= 1) s += __shfl_xor_sync(~0u, s, o);
    float p = e / s;

    unsigned long long key = ((unsigned long long)ordu(p) << 32) | (unsigned)(~lane);
    key = warp_sort_desc(key, lane);

    float pv = unordu((unsigned)(key >> 32));
    float p0 = __shfl_sync(~0u, pv, 0);
    float ev = (lane < TK) ? expf(pv - p0) : 0.f;
    float ssum = ev;
#pragma unroll
    for (int o = 16; o; o >>= 1) ssum += __shfl_xor_sync(~0u, ssum, o);
    float wnorm = ev / ssum;

    const float4* H = (const float4*)g_newh;
    int base = half * 32;
    float4 acc = H[(size_t)n * 64 + base + lane];
#pragma unroll
    for (int i = 0; i < TK; i++) {
        unsigned long long ki = __shfl_sync(~0u, key, i);
        int wl = (int)((~(unsigned)ki) & 31u);
        int node = __shfl_sync(~0u, j, wl);
        float wi = __shfl_sync(~0u, wnorm, i);
        float4 v = H[(size_t)node * 64 + base + lane];
        acc.x = fmaf(wi, v.x, acc.x); acc.y = fmaf(wi, v.y, acc.y);
        acc.z = fmaf(wi, v.z, acc.z); acc.w = fmaf(wi, v.w, acc.w);
    }
    ((float4*)g_finalpre)[(size_t)n * 64 + base + lane] = acc;
}

// =====================================================================================
// fused STAGE2 + BNSUM kernel (independent work, complementary bottlenecks):
//   blocks [0, nbS2): stage-2 32-way merge (REDUX-accelerated pops, SDEPTH-staged lists)
//   blocks [nbS2, nbS2+NBBN): batchnorm sums (memory-latency-bound, 2 cols/thread)
// =====================================================================================
__global__ __launch_bounds__(128, 10) void k_stage2_bnsum(const int* __restrict__ rf,
                                                          float* __restrict__ out2, int N, int write2) {
    __shared__ unsigned long long s[4][RR * SSTR];
    int nbS2 = (N + 3) / 4;

    if ((int)blockIdx.x >= nbS2) {
        // ---- bnsum: f32 accumulators (2 cols x 2 row-chains), f64 only at the atomic ----
        int f = threadIdx.x;                 // column pair: f and f+128
        int bb = blockIdx.x - nbS2;
        int stride = NBBN;
        float sA = 0.f, sB = 0.f, sC = 0.f, sD = 0.f;
        float qA = 0.f, qB = 0.f, qC = 0.f, qD = 0.f;
        int r = bb;
        for (; r + stride < N; r += 2 * stride) {
            float v0 = g_finalpre[(size_t)r * FO + f];
            float v1 = g_finalpre[(size_t)r * FO + f + 128];
            float v2 = g_finalpre[(size_t)(r + stride) * FO + f];
            float v3 = g_finalpre[(size_t)(r + stride) * FO + f + 128];
            sA += v0; qA = fmaf(v0, v0, qA);
            sB += v1; qB = fmaf(v1, v1, qB);
            sC += v2; qC = fmaf(v2, v2, qC);
            sD += v3; qD = fmaf(v3, v3, qD);
        }
        for (; r < N; r += stride) {
            float v0 = g_finalpre[(size_t)r * FO + f];
            float v1 = g_finalpre[(size_t)r * FO + f + 128];
            sA += v0; qA = fmaf(v0, v0, qA);
            sB += v1; qB = fmaf(v1, v1, qB);
        }
        atomicAdd(&g_sum[f], (double)(sA + sC));
        atomicAdd(&g_sum[f + 128], (double)(sB + sD));
        atomicAdd(&g_sumsq[f], (double)(qA + qC));
        atomicAdd(&g_sumsq[f + 128], (double)(qB + qD));
        return;
    }

    // ---- stage2: 32-way merge of pre-sorted adj rows, warp-per-row ----
    // order = (sk desc, global position asc) == lexicographic (hi=sk, lo=1024-pos) max.
    // REDUX.MAX.U32 replaces the 5-stage shfl tree (same exact max -> identical selection).
    int w = threadIdx.x >> 5, lane = threadIdx.x & 31;
    int n = blockIdx.x * 4 + w;
    if (n >= N) return;
    int rfv = rf[(size_t)n * RR + lane];
    if (write2) out2[(size_t)n * RR + lane] = (float)rfv;  // copy of receptive_field slab

    unsigned long long* sw = s[w];
#pragma unroll
    for (int r = 0; r < RR; r++) {
        int row = __shfl_sync(~0u, rfv, r);
        if (lane < SDEPTH)
            sw[r * SSTR + lane] = g_adjsorted[(size_t)row * RR + lane];   // head of each list
    }
    __syncwarp();

    const unsigned long long* mylist = sw + lane * SSTR;
    const unsigned long long* gml = &g_adjsorted[(size_t)rfv * RR];  // overflow fallback (same data)
    int idx = 0;
    unsigned long long e = mylist[0];
    int basepos = 1024 - lane * RR;
    int d = 31 - (int)((e >> 26) & 31u);
    unsigned hi = (unsigned)(e >> 32);
    unsigned lo = (unsigned)(basepos - d);

    float* oute = out2 + (size_t)N * RR;
    for (int i = 0; i < RR; i++) {
        unsigned mh = __reduce_max_sync(~0u, hi);
        unsigned ball = __ballot_sync(~0u, hi == mh);
        bool win;
        if (__popc(ball) == 1) {
            win = (hi == mh);
        } else {
            unsigned lom = __reduce_max_sync(~0u, (hi == mh) ? lo : 0u);
            win = (hi == mh) && (lo == lom);   // lo unique among tied -> exactly one winner
        }
        if (win) {
            if (write2) oute[(size_t)n * RR + i] = (float)(unsigned)(e & 0x3FFFFFFu);
            idx++;
            if (idx < RR) {
                e = (idx < SDEPTH) ? mylist[idx] : gml[idx];   // rare overflow -> L2 (identical bits)
                d = 31 - (int)((e >> 26) & 31u);
                hi = (unsigned)(e >> 32);
                lo = (unsigned)(basepos - d);
            } else {
                hi = 0u; lo = 0u;              // exhausted (cannot win mid-loop; safe floor)
            }
        }
    }
}

// ---------------- batchnorm finalize + apply: full residency + 2-way unrolled stream ----------------
__global__ __launch_bounds__(256) void k_bnapply(const float* __restrict__ gamma,
                                                 const float* __restrict__ beta,
                                                 float* __restrict__ out, int N) {
    __shared__ float sc[FO], sh[FO];
    int t = threadIdx.x;
    {
        double mean = g_sum[t] / (double)N;
        double var = g_sumsq[t] / (double)N - mean * mean;
        float inv = rsqrtf((float)var + 1e-5f);
        float scv = gamma[t] * inv;
        sc[t] = scv;
        sh[t] = beta[t] - (float)mean * scv;
    }
    __syncthreads();
    size_t total = (size_t)N * 64;
    size_t step = (size_t)gridDim.x * 256;
    size_t i = (size_t)blockIdx.x * 256 + t;
    for (; i + step < total; i += 2 * step) {
        float4 v0 = ((const float4*)g_finalpre)[i];
        float4 v1 = ((const float4*)g_finalpre)[i + step];
        int c0 = ((int)(i & 63)) * 4;
        int c1 = ((int)((i + step) & 63)) * 4;
        v0.x = fmaxf(fmaf(v0.x, sc[c0 + 0], sh[c0 + 0]), 0.f);
        v0.y = fmaxf(fmaf(v0.y, sc[c0 + 1], sh[c0 + 1]), 0.f);
        v0.z = fmaxf(fmaf(v0.z, sc[c0 + 2], sh[c0 + 2]), 0.f);
        v0.w = fmaxf(fmaf(v0.w, sc[c0 + 3], sh[c0 + 3]), 0.f);
        v1.x = fmaxf(fmaf(v1.x, sc[c1 + 0], sh[c1 + 0]), 0.f);
        v1.y = fmaxf(fmaf(v1.y, sc[c1 + 1], sh[c1 + 1]), 0.f);
        v1.z = fmaxf(fmaf(v1.z, sc[c1 + 2], sh[c1 + 2]), 0.f);
        v1.w = fmaxf(fmaf(v1.w, sc[c1 + 3], sh[c1 + 3]), 0.f);
        ((float4*)out)[i] = v0;
        ((float4*)out)[i + step] = v1;
    }
    for (; i < total; i += step) {
        float4 v = ((const float4*)g_finalpre)[i];
        int c = ((int)(i & 63)) * 4;
        v.x = fmaxf(fmaf(v.x, sc[c + 0], sh[c + 0]), 0.f);
        v.y = fmaxf(fmaf(v.y, sc[c + 1], sh[c + 1]), 0.f);
        v.z = fmaxf(fmaf(v.z, sc[c + 2], sh[c + 2]), 0.f);
        v.w = fmaxf(fmaf(v.w, sc[c + 3], sh[c + 3]), 0.f);
        ((float4*)out)[i] = v;
    }
}

// ---------------- launch ----------------
extern "C" void kernel_launch(void* const* d_in, const int* in_sizes, int n_in,
                              void* d_out, int out_size) {
    const float* x    = (const float*)d_in[0];
    const int*   rf   = (const int*)d_in[1];
    const int*   adj  = (const int*)d_in[2];
    const float* W    = (const float*)d_in[3];
    const float* B    = (const float*)d_in[4];
    const float* Wk   = (const float*)d_in[5];
    const float* Bk   = (const float*)d_in[6];
    const float* Wq   = (const float*)d_in[7];
    const float* Bq   = (const float*)d_in[8];
    const float* la   = (const float*)d_in[9];
    const float* Bla  = (const float*)d_in[11];
    const float* gamma= (const float*)d_in[13];
    const float* beta = (const float*)d_in[14];

    int N = in_sizes[0] / FI;
    if (N > MAXN) return;
    float* out = (float*)d_out;
    long need2 = (long)N * FO + 2L * N * RR;
    int write2 = (out_size >= need2) ? 1 : 0;

    dim3 gg((N + 63) / 64, 5);               // y 0..3: gemm tiles, y==4: kq
    k_gemm_kq<<<gg, 128>>>(x, W, B, Wk, Bk, Wq, Bq, N);
    k_las<<<(N + 63) / 64, 256>>>(la, Bla, N);
    int nbSort = (N + 7) / 8, nbAtt = (N + 3) / 4;
    k_att_sortadj<<<nbSort + nbAtt, 256>>>(rf, adj, N);
    int nbS2 = (N + 3) / 4;
    k_stage2_bnsum<<<nbS2 + NBBN, 128>>>(rf, out + (size_t)N * FO, N, write2);
    k_bnapply<<<1184, 256>>>(gamma, beta, out, N);
}